// round 1
// baseline (speedup 1.0000x reference)
#include <cuda_runtime.h>
#include <math.h>

#define N_ANGLES 128
#define N_SIZE   128
#define NCH      1024          // 8 * 128  (c,h) slices
#define NI       16            // feature angle samples
#define WW       128           // detector width
#define PADL     32
#define TABW     192           // padded window [-32, 160)

// scratch (static device arrays: allocation-free)
__device__ float  g_h[256];                         // doubled ramp taps
__device__ float  g_G[NI * NCH * WW];               // 8 MB   filtered features
__device__ float2 g_T[NCH * N_ANGLES * TABW];       // 201 MB (q,d) gather table

// ---------------- K1: ramp filter taps h[n] = (1/128) sum_k f_k cos(2pi k n/128)
__global__ void k_taps() {
    int n = threadIdx.x;               // 0..127
    float s = 0.0f;
    for (int k = 0; k < 128; k++) {
        float fk = (float)min(k, 128 - k) * (1.0f / 128.0f);
        int m = (k * n) & 127;         // exact arg reduction
        s += fk * cosf((float)m * 0.049087385212340526f);   // 2*pi/128
    }
    s *= (1.0f / 128.0f);
    g_h[n] = s;
    g_h[n + 128] = s;
}

// ---------------- K2: G[i][ch][w] = circular conv of feature row with h
__global__ void k_filter(const float* __restrict__ feat) {
    __shared__ float row[128];
    __shared__ float h2[256];
    int b = blockIdx.x;                // i*1024 + ch, 16384 blocks
    int t = threadIdx.x;               // 0..127
    row[t] = feat[b * 128 + t];
    h2[t] = g_h[t];
    h2[t + 128] = g_h[t + 128];
    __syncthreads();
    float acc = 0.0f;
#pragma unroll 8
    for (int wp = 0; wp < 128; wp++)
        acc = fmaf(row[wp], h2[t - wp + 128], acc);
    g_G[b * 128 + t] = acc;
}

// ---------------- K3: build padded (q,d) table, fusing the angle-lerp
__global__ void k_table() {
    int gid = blockIdx.x * 256 + threadIdx.x;
    if (gid >= NCH * N_ANGLES * TABW) return;
    int wq   = gid % TABW;
    int rest = gid / TABW;
    int a    = rest % N_ANGLES;
    int ch   = rest / N_ANGLES;

    int   i0g = a >> 3;
    int   i1g = (i0g + 1) & 15;        // wraps to features[0] (stacked[16])
    float wa  = (float)(a & 7) * 0.125f;

    const float* G0 = g_G + (i0g * NCH + ch) * WW;
    const float* G1 = g_G + (i1g * NCH + ch) * WW;

    int wi = wq - PADL;
    float f0 = 0.0f, f1 = 0.0f;
    if (wi >= 0 && wi < WW)
        f0 = fmaf(G1[wi] - G0[wi], wa, G0[wi]);
    int wi1 = wi + 1;
    if (wi1 >= 0 && wi1 < WW)
        f1 = fmaf(G1[wi1] - G0[wi1], wa, G0[wi1]);

    g_T[gid] = make_float2(0.5f * (f0 + f1), f1 - f0);   // (q, d)
}

// ---------------- K4: backprojection, one (c,h) slice per block
__global__ void __launch_bounds__(512, 1) k_backproj(float* __restrict__ out) {
    extern __shared__ float4 smem4[];              // (q,d) table: 128 x 192 float2
    __shared__ float2 sc[128];                     // (cos, sin) per angle
    int ch  = blockIdx.x;
    int tid = threadIdx.x;

    // bulk-load this slice's table (196608 B, float4 copies)
    const float4* src = (const float4*)(g_T + ch * (N_ANGLES * TABW));
    for (int k = tid; k < N_ANGLES * TABW / 2; k += 512)
        smem4[k] = src[k];
    if (tid < 128) {
        float ang = (float)tid * 0.024543692603601845f;   // pi/128, matches np.float32
        float sv, cv;
        sincosf(ang, &sv, &cv);
        sc[tid] = make_float2(cv, sv);
    }
    __syncthreads();

    const float2* tab = (const float2*)smem4;
    int l     = tid & 31;
    int wid   = tid >> 5;                 // 0..15
    int y     = ((wid & 3) << 5) + l;     // lanes = consecutive y -> LDS broadcast dedup
    float yc  = (float)y - 63.5f;
    int xbase = wid >> 2;                 // 0..3 ; thread covers x = xbase + 4*i

    float acc[32];
#pragma unroll
    for (int i = 0; i < 32; i++) acc[i] = 0.0f;

    const float MAGIC = 12582912.0f;      // 2^23 + 2^22

    for (int a = 0; a < N_ANGLES; a++) {
        float cv = sc[a].x, sv = sc[a].y;
        const float2* row = tab + a * TABW + PADL;
        // u' = u - 0.5 = xc*cos + yc*sin + 63.0 ; march in x by step = 4*cos
        float u    = fmaf((float)xbase - 63.5f, cv, fmaf(yc, sv, 63.0f));
        float step = 4.0f * cv;
#pragma unroll
        for (int i = 0; i < 32; i++) {
            float m   = u + MAGIC;                    // round(u') into mantissa
            float i0f = m - MAGIC;                    // floor(u) (ties harmless)
            float fr  = u - i0f;                      // in [-0.5, 0.5]
            int   i0  = __float_as_int(m) - 0x4B400000;
            float2 p  = row[i0];                      // one LDS.64: (q, d)
            acc[i] = fmaf(fr, p.y, acc[i] + p.x);     // f0 + frac*d accumulated
            u += step;
        }
    }

    const float scale = 0.024543692603601845f;        // pi/128
    float* o = out + ch * 16384 + y;
#pragma unroll
    for (int i = 0; i < 32; i++) {
        int x = xbase + 4 * i;
        o[x * 128] = acc[i] * scale;                  // coalesced across lanes (y)
    }
}

extern "C" void kernel_launch(void* const* d_in, const int* in_sizes, int n_in,
                              void* d_out, int out_size) {
    const float* feat = (const float*)d_in[0];
    float* out = (float*)d_out;

    cudaFuncSetAttribute(k_backproj, cudaFuncAttributeMaxDynamicSharedMemorySize,
                         N_ANGLES * TABW * (int)sizeof(float2));

    k_taps<<<1, 128>>>();
    k_filter<<<NI * NCH, 128>>>(feat);
    k_table<<<(NCH * N_ANGLES * TABW + 255) / 256, 256>>>();
    k_backproj<<<NCH, 512, N_ANGLES * TABW * sizeof(float2)>>>(out);
}

// round 2
// speedup vs baseline: 1.2237x; 1.2237x over previous
#include <cuda_runtime.h>
#include <math.h>

#define N_ANGLES 128
#define NCH      1024          // 8 * 128  (c,h) slices
#define NI       16            // feature angle samples
#define WW       128           // detector width
#define PADL     32
#define TABW     192           // padded window [-32, 160)

__device__ float g_h[256];                 // doubled ramp taps
__device__ float g_G[NI * NCH * WW];       // 8 MB filtered features

// ---- packed f32x2 helpers (sm_103a) ----
__device__ __forceinline__ unsigned long long pk2(float lo, float hi) {
    unsigned long long r;
    asm("mov.b64 %0, {%1, %2};" : "=l"(r) : "f"(lo), "f"(hi));
    return r;
}
__device__ __forceinline__ void upk2(unsigned long long v, float& lo, float& hi) {
    asm("mov.b64 {%0, %1}, %2;" : "=f"(lo), "=f"(hi) : "l"(v));
}
__device__ __forceinline__ unsigned long long add2(unsigned long long a, unsigned long long b) {
    unsigned long long r;
    asm("add.rn.f32x2 %0, %1, %2;" : "=l"(r) : "l"(a), "l"(b));
    return r;
}
__device__ __forceinline__ unsigned long long fma2(unsigned long long a, unsigned long long b,
                                                   unsigned long long c) {
    unsigned long long r;
    asm("fma.rn.f32x2 %0, %1, %2, %3;" : "=l"(r) : "l"(a), "l"(b), "l"(c));
    return r;
}

// ---------------- K1: ramp filter taps h[n] = (1/128) sum_k f_k cos(2pi k n/128)
__global__ void k_taps() {
    int n = threadIdx.x;
    float s = 0.0f;
    for (int k = 0; k < 128; k++) {
        float fk = (float)min(k, 128 - k) * (1.0f / 128.0f);
        int m = (k * n) & 127;
        s += fk * cosf((float)m * 0.049087385212340526f);   // 2*pi/128
    }
    s *= (1.0f / 128.0f);
    g_h[n] = s;
    g_h[n + 128] = s;
}

// ---------------- K2: G[i][ch][w] = circular conv of feature row with h
__global__ void k_filter(const float* __restrict__ feat) {
    __shared__ float row[128];
    __shared__ float h2[256];
    int b = blockIdx.x;
    int t = threadIdx.x;
    row[t] = feat[b * 128 + t];
    h2[t] = g_h[t];
    h2[t + 128] = g_h[t + 128];
    __syncthreads();
    float acc = 0.0f;
#pragma unroll 8
    for (int wp = 0; wp < 128; wp++)
        acc = fmaf(row[wp], h2[t - wp + 128], acc);
    g_G[b * 128 + t] = acc;
}

// ---------------- K3+K4 fused: build (q,d) table in smem, then backproject
__global__ void __launch_bounds__(512, 1) k_backproj(float* __restrict__ out) {
    extern __shared__ float2 tab[];                 // 128 angles x 192 entries
    __shared__ float  sG[17 * 128];                 // staged filtered features
    __shared__ float2 sc[128];                      // (cos, sin) per angle
    int ch  = blockIdx.x;
    int tid = threadIdx.x;

    // stage G rows (i = 0..16, row 16 wraps to row 0)
    for (int k = tid; k < 17 * 128; k += 512) {
        int i = k >> 7;
        int w = k & 127;
        int ig = (i == 16) ? 0 : i;
        sG[k] = g_G[(ig * NCH + ch) * WW + w];
    }
    if (tid < 128) {
        float ang = (float)tid * 0.024543692603601845f;   // pi/128
        float sv, cv;
        sincosf(ang, &sv, &cv);
        sc[tid] = make_float2(cv, sv);
    }
    __syncthreads();

    // build padded (q,d) table: fuse the angle-lerp
    for (int e = tid; e < N_ANGLES * TABW; e += 512) {
        int a  = e / TABW;
        int wq = e - a * TABW;
        int   i0g = a >> 3;
        float wa  = (float)(a & 7) * 0.125f;
        const float* G0 = sG + (i0g << 7);            // rows i0g and i0g+1 (wrap ok)
        int wi = wq - PADL;
        float f0 = 0.0f, f1 = 0.0f;
        if (wi >= 0 && wi < WW)
            f0 = fmaf(G0[wi + 128] - G0[wi], wa, G0[wi]);
        int wi1 = wi + 1;
        if (wi1 >= 0 && wi1 < WW)
            f1 = fmaf(G0[wi1 + 128] - G0[wi1], wa, G0[wi1]);
        tab[e] = make_float2(0.5f * (f0 + f1), f1 - f0);
    }
    __syncthreads();

    int l     = tid & 31;
    int wid   = tid >> 5;                 // 0..15
    int y     = ((wid & 3) << 5) + l;     // lanes = consecutive y
    float yc  = (float)y - 63.5f;
    int xbase = wid >> 2;                 // 0..3 ; thread covers x = xbase + 4*i

    float acc[32];
#pragma unroll
    for (int i = 0; i < 32; i++) acc[i] = 0.0f;

    const float MAGIC = 12582912.0f;      // 2^23 + 2^22
    const unsigned long long M2   = pk2(MAGIC, MAGIC);
    const unsigned long long NM2  = pk2(-MAGIC, -MAGIC);
    const unsigned long long NEG1 = pk2(-1.0f, -1.0f);

    for (int a = 0; a < N_ANGLES; a++) {
        float cv = sc[a].x, sv = sc[a].y;
        const float2* row = tab + a * TABW + PADL;
        // u' = u - 0.5 = xc*cos + yc*sin + 63.0
        float ua = fmaf((float)xbase - 63.5f, cv, fmaf(yc, sv, 63.0f));
        float ub = fmaf(4.0f, cv, ua);
        unsigned long long u2    = pk2(ua, ub);
        unsigned long long step2 = pk2(8.0f * cv, 8.0f * cv);
#pragma unroll
        for (int j = 0; j < 16; j++) {
            unsigned long long m2   = add2(u2, M2);     // round into mantissa
            unsigned long long i0f2 = add2(m2, NM2);    // rni(u') as float
            unsigned long long fr2  = fma2(i0f2, NEG1, u2);  // u' - rni(u')  in [-.5,.5]
            u2 = add2(u2, step2);

            float mA, mB, frA, frB;
            upk2(m2, mA, mB);
            upk2(fr2, frA, frB);
            int iA = __float_as_int(mA) - 0x4B400000;
            int iB = __float_as_int(mB) - 0x4B400000;
            float2 pA = row[iA];                        // one LDS.64 each
            float2 pB = row[iB];
            acc[2 * j]     = fmaf(frA, pA.y, acc[2 * j]     + pA.x);
            acc[2 * j + 1] = fmaf(frB, pB.y, acc[2 * j + 1] + pB.x);
        }
    }

    const float scale = 0.024543692603601845f;        // pi/128
    float* o = out + ch * 16384 + y;
#pragma unroll
    for (int i = 0; i < 32; i++) {
        int x = xbase + 4 * i;
        o[x * 128] = acc[i] * scale;                  // coalesced across lanes (y)
    }
}

extern "C" void kernel_launch(void* const* d_in, const int* in_sizes, int n_in,
                              void* d_out, int out_size) {
    const float* feat = (const float*)d_in[0];
    float* out = (float*)d_out;

    cudaFuncSetAttribute(k_backproj, cudaFuncAttributeMaxDynamicSharedMemorySize,
                         N_ANGLES * TABW * (int)sizeof(float2));

    k_taps<<<1, 128>>>();
    k_filter<<<NI * NCH, 128>>>(feat);
    k_backproj<<<NCH, 512, N_ANGLES * TABW * sizeof(float2)>>>(out);
}